// round 5
// baseline (speedup 1.0000x reference)
#include <cuda_runtime.h>
#include <cuda_bf16.h>

// GCNLayer SpMM: out[i,:] = sum_{e: rows[e]==i} vals[e] * embeds[cols[e],:]
// N=10000 nodes, E=640000 edges, D=128 features.
//
// Round-3 design: counting-sort preprocessing with 8-way REPLICATED
// counters/cursors to break per-address atomic serialization (round-2's
// scatter spent 18us on 64-deep contended atomicAdd-with-return). Then
// warp-per-row CSR SpMM (register accumulation, zero atomics), which is
// L2-read-bound at ~328MB ~= 28us.

static constexpr int MAX_N = 10000;
static constexpr int MAX_E = 640000;
static constexpr int D_VEC = 32;           // 128 floats = 32 float4 per row
static constexpr int C_REP = 8;            // counter replication factor

__device__ int   g_count[C_REP * MAX_N];   // per-replica histograms
__device__ int   g_cursor[C_REP * MAX_N];  // per-replica staggered cursors
__device__ int   g_start[MAX_N + 1];       // CSR row offsets
__device__ uint2 g_pairs[MAX_E];           // .x = col, .y = bits(val), row-sorted

__device__ __forceinline__ int replica_of(int e) { return (e >> 8) & (C_REP - 1); }

// ---------------------------------------------------------------- kernel 1
__global__ void zero_counts_kernel(int total) {
    int i = blockIdx.x * blockDim.x + threadIdx.x;
    if (i < total) g_count[i] = 0;
}

// ---------------------------------------------------------------- kernel 2
// No-return atomicAdd -> compiler emits RED (fast under contention).
__global__ void hist_kernel(const int* __restrict__ rows, int E) {
    int e = blockIdx.x * blockDim.x + threadIdx.x;
    if (e < E) {
        int r = rows[e];
        int c = replica_of(e);
        atomicAdd(&g_count[c * MAX_N + r], 1);
    }
}

// ---------------------------------------------------------------- kernel 3
// One-block scan: row totals -> g_start; staggered per-replica cursors.
static constexpr int SCAN_THREADS = 1024;
static constexpr int SCAN_ITEMS   = 10;     // covers up to 10240 rows

__global__ __launch_bounds__(SCAN_THREADS) void scan_kernel(int n) {
    __shared__ int partial[SCAN_THREADS];
    int tid  = threadIdx.x;
    int base = tid * SCAN_ITEMS;

    int rep_cnt[SCAN_ITEMS][C_REP];
    int local[SCAN_ITEMS];
    int sum = 0;
    #pragma unroll
    for (int i = 0; i < SCAN_ITEMS; i++) {
        int r = base + i;
        int tot = 0;
        if (r < n) {
            #pragma unroll
            for (int c = 0; c < C_REP; c++) {
                int v = g_count[c * MAX_N + r];
                rep_cnt[i][c] = v;
                tot += v;
            }
        }
        local[i] = sum;             // exclusive within this thread's chunk
        sum += tot;
    }
    partial[tid] = sum;
    __syncthreads();

    // Hillis-Steele inclusive scan over per-thread sums
    for (int off = 1; off < SCAN_THREADS; off <<= 1) {
        int t = (tid >= off) ? partial[tid - off] : 0;
        __syncthreads();
        partial[tid] += t;
        __syncthreads();
    }

    int prefix = (tid > 0) ? partial[tid - 1] : 0;   // exclusive across threads
    #pragma unroll
    for (int i = 0; i < SCAN_ITEMS; i++) {
        int r = base + i;
        if (r < n) {
            int s = prefix + local[i];
            g_start[r] = s;
            int cur = s;
            #pragma unroll
            for (int c = 0; c < C_REP; c++) {
                g_cursor[c * MAX_N + r] = cur;
                cur += rep_cnt[i][c];
            }
        }
    }
    if (tid == SCAN_THREADS - 1) g_start[n] = partial[SCAN_THREADS - 1];
}

// ---------------------------------------------------------------- kernel 4
// Returning atomic, but contention is 8-deep over 80K addresses now.
__global__ void scatter_kernel(const int*   __restrict__ rows,
                               const int*   __restrict__ cols,
                               const float* __restrict__ vals,
                               int E) {
    int e = blockIdx.x * blockDim.x + threadIdx.x;
    if (e >= E) return;
    int r = rows[e];
    int c = replica_of(e);
    int pos = atomicAdd(&g_cursor[c * MAX_N + r], 1);
    g_pairs[pos] = make_uint2((unsigned)cols[e], __float_as_uint(vals[e]));
}

// ---------------------------------------------------------------- kernel 5
// Warp per row: lane owns one float4 (16B) chunk of the 512B output row.
__global__ __launch_bounds__(256) void spmm_csr_kernel(
    const float4* __restrict__ emb,    // [N, 32] float4
    float4*       __restrict__ out,    // [N, 32] float4
    int n)
{
    int warp = (blockIdx.x * blockDim.x + threadIdx.x) >> 5;
    int lane = threadIdx.x & 31;
    if (warp >= n) return;

    int j   = g_start[warp];
    int end = g_start[warp + 1];

    float4 acc = make_float4(0.f, 0.f, 0.f, 0.f);

    // Full 32-edge chunks: coalesced pair load, unrolled shfl broadcast so
    // gather LDG.128s batch up for MLP.
    while (end - j >= 32) {
        uint2 p = g_pairs[j + lane];
        #pragma unroll 8
        for (int k = 0; k < 32; k++) {
            int   c = __shfl_sync(0xffffffffu, (int)p.x, k);
            float v = __uint_as_float(__shfl_sync(0xffffffffu, p.y, k));
            float4 x = __ldg(emb + c * D_VEC + lane);
            acc.x += v * x.x; acc.y += v * x.y;
            acc.z += v * x.z; acc.w += v * x.w;
        }
        j += 32;
    }

    // Remainder
    int m = end - j;
    if (m > 0) {
        uint2 p = (lane < m) ? g_pairs[j + lane] : make_uint2(0u, 0u);
        for (int k = 0; k < m; k++) {
            int   c = __shfl_sync(0xffffffffu, (int)p.x, k);
            float v = __uint_as_float(__shfl_sync(0xffffffffu, p.y, k));
            float4 x = __ldg(emb + c * D_VEC + lane);
            acc.x += v * x.x; acc.y += v * x.y;
            acc.z += v * x.z; acc.w += v * x.w;
        }
    }

    out[warp * D_VEC + lane] = acc;   // rows with no edges write zeros
}

// ----------------------------------------------------------------- launch
extern "C" void kernel_launch(void* const* d_in, const int* in_sizes, int n_in,
                              void* d_out, int out_size) {
    const int*   adj_rows = (const int*)  d_in[0];
    const int*   adj_cols = (const int*)  d_in[1];
    const float* adj_vals = (const float*)d_in[2];
    const float* embeds   = (const float*)d_in[3];
    float*       out      = (float*)d_out;

    const int E = in_sizes[0];           // 640000
    const int N = out_size / 128;        // 10000

    zero_counts_kernel<<<(C_REP * N + 255) / 256, 256>>>(C_REP * N);
    hist_kernel<<<(E + 255) / 256, 256>>>(adj_rows, E);
    scan_kernel<<<1, SCAN_THREADS>>>(N);
    scatter_kernel<<<(E + 255) / 256, 256>>>(adj_rows, adj_cols, adj_vals, E);

    long long total_threads = (long long)N * 32;
    int blocks = (int)((total_threads + 255) / 256);
    spmm_csr_kernel<<<blocks, 256>>>((const float4*)embeds, (float4*)out, N);
}

// round 6
// speedup vs baseline: 1.7738x; 1.7738x over previous
#include <cuda_runtime.h>
#include <cuda_bf16.h>

// GCNLayer SpMM: out[i,:] = sum_{e: rows[e]==i} vals[e] * embeds[cols[e],:]
// N=10000 nodes, E=640000 edges, D=128 features.
//
// Round-6: counting-sort CSR build with 32-way replicated counters/cursors
// (replica = e&31 -> zero intra-warp same-address atomic conflicts, ~2-deep
// contention). All replica reduction/staggering in full-grid coalesced
// kernels; the single-block scan is smem-staged and register-light (round-5's
// 102us regression was a register-spilled single-block scan). Main SpMM pass:
// warp-per-row CSR gather, register accumulation, zero atomics -> L2-read
// floor ~29us.

static constexpr int MAX_N = 10000;
static constexpr int MAX_E = 640000;
static constexpr int D_VEC = 32;           // 128 floats = 32 float4 per row
static constexpr int C_REP = 32;           // counter replication factor

__device__ int   g_count[C_REP * MAX_N];   // per-replica histograms
__device__ int   g_cursor[C_REP * MAX_N];  // per-replica staggered cursors
__device__ int   g_total[MAX_N];           // per-row totals
__device__ int   g_start[MAX_N + 1];       // CSR row offsets
__device__ uint2 g_pairs[MAX_E];           // .x = col, .y = bits(val), row-sorted

// ---------------------------------------------------------------- hist
// No-return atomicAdd -> RED. replica = e&31: every lane in a warp uses a
// different replica bank, so no intra-warp same-address conflicts.
__global__ void hist_kernel(const int* __restrict__ rows, int E) {
    int e = blockIdx.x * blockDim.x + threadIdx.x;
    if (e < E) {
        int r = rows[e];
        atomicAdd(&g_count[(e & (C_REP - 1)) * MAX_N + r], 1);
    }
}

// ---------------------------------------------------------------- reduce
// total[r] = sum_c count[c][r]; coalesced (warp reads consecutive r).
__global__ void reduce_kernel(int n) {
    int r = blockIdx.x * blockDim.x + threadIdx.x;
    if (r >= n) return;
    int t = 0;
    #pragma unroll
    for (int c = 0; c < C_REP; c++) t += g_count[c * MAX_N + r];
    g_total[r] = t;
}

// ---------------------------------------------------------------- scan
// Single block, smem-staged so all gmem traffic is coalesced and the only
// per-thread register array is loc[10].
static constexpr int SCAN_THREADS = 1024;
static constexpr int SCAN_ITEMS   = 10;     // 10240 >= N
static constexpr int SCAN_SPAN    = SCAN_THREADS * SCAN_ITEMS;

__global__ __launch_bounds__(SCAN_THREADS) void scan_kernel(int n) {
    __shared__ int s_val[SCAN_SPAN];
    __shared__ int s_part[SCAN_THREADS];
    int tid = threadIdx.x;

    for (int i = tid; i < SCAN_SPAN; i += SCAN_THREADS)
        s_val[i] = (i < n) ? g_total[i] : 0;
    __syncthreads();

    int base = tid * SCAN_ITEMS;
    int loc[SCAN_ITEMS];
    int sum = 0;
    #pragma unroll
    for (int i = 0; i < SCAN_ITEMS; i++) { loc[i] = sum; sum += s_val[base + i]; }
    s_part[tid] = sum;
    __syncthreads();

    for (int off = 1; off < SCAN_THREADS; off <<= 1) {
        int t = (tid >= off) ? s_part[tid - off] : 0;
        __syncthreads();
        s_part[tid] += t;
        __syncthreads();
    }

    int prefix = (tid > 0) ? s_part[tid - 1] : 0;
    #pragma unroll
    for (int i = 0; i < SCAN_ITEMS; i++) s_val[base + i] = prefix + loc[i];
    __syncthreads();

    for (int i = tid; i < n; i += SCAN_THREADS) g_start[i] = s_val[i];
    if (tid == SCAN_THREADS - 1) g_start[n] = s_part[SCAN_THREADS - 1];
}

// ---------------------------------------------------------------- stagger
// cursor[c][r] = start[r] + sum_{c'<c} count[c'][r]; coalesced per c.
__global__ void stagger_kernel(int n) {
    int r = blockIdx.x * blockDim.x + threadIdx.x;
    if (r >= n) return;
    int cur = g_start[r];
    #pragma unroll
    for (int c = 0; c < C_REP; c++) {
        g_cursor[c * MAX_N + r] = cur;
        cur += g_count[c * MAX_N + r];
    }
}

// ---------------------------------------------------------------- scatter
// Returning atomic, but contention ~2-deep over 320K cursor addresses.
__global__ void scatter_kernel(const int*   __restrict__ rows,
                               const int*   __restrict__ cols,
                               const float* __restrict__ vals,
                               int E) {
    int e = blockIdx.x * blockDim.x + threadIdx.x;
    if (e >= E) return;
    int r = rows[e];
    int pos = atomicAdd(&g_cursor[(e & (C_REP - 1)) * MAX_N + r], 1);
    g_pairs[pos] = make_uint2((unsigned)cols[e], __float_as_uint(vals[e]));
}

// ---------------------------------------------------------------- spmm
// Warp per row: lane owns one float4 (16B) chunk of the 512B output row.
__global__ __launch_bounds__(256) void spmm_csr_kernel(
    const float4* __restrict__ emb,    // [N, 32] float4
    float4*       __restrict__ out,    // [N, 32] float4
    int n)
{
    int warp = (blockIdx.x * blockDim.x + threadIdx.x) >> 5;
    int lane = threadIdx.x & 31;
    if (warp >= n) return;

    int j   = g_start[warp];
    int end = g_start[warp + 1];

    float4 acc = make_float4(0.f, 0.f, 0.f, 0.f);

    while (end - j >= 32) {
        uint2 p = g_pairs[j + lane];
        #pragma unroll 8
        for (int k = 0; k < 32; k++) {
            int   c = __shfl_sync(0xffffffffu, (int)p.x, k);
            float v = __uint_as_float(__shfl_sync(0xffffffffu, p.y, k));
            float4 x = __ldg(emb + c * D_VEC + lane);
            acc.x += v * x.x; acc.y += v * x.y;
            acc.z += v * x.z; acc.w += v * x.w;
        }
        j += 32;
    }

    int m = end - j;
    if (m > 0) {
        uint2 p = (lane < m) ? g_pairs[j + lane] : make_uint2(0u, 0u);
        for (int k = 0; k < m; k++) {
            int   c = __shfl_sync(0xffffffffu, (int)p.x, k);
            float v = __uint_as_float(__shfl_sync(0xffffffffu, p.y, k));
            float4 x = __ldg(emb + c * D_VEC + lane);
            acc.x += v * x.x; acc.y += v * x.y;
            acc.z += v * x.z; acc.w += v * x.w;
        }
    }

    out[warp * D_VEC + lane] = acc;   // rows with no edges write zeros
}

// ----------------------------------------------------------------- launch
extern "C" void kernel_launch(void* const* d_in, const int* in_sizes, int n_in,
                              void* d_out, int out_size) {
    const int*   adj_rows = (const int*)  d_in[0];
    const int*   adj_cols = (const int*)  d_in[1];
    const float* adj_vals = (const float*)d_in[2];
    const float* embeds   = (const float*)d_in[3];
    float*       out      = (float*)d_out;

    const int E = in_sizes[0];           // 640000
    const int N = out_size / 128;        // 10000

    // Zero the replicated histograms via a memset node (capture-legal).
    void* count_ptr = nullptr;
    cudaGetSymbolAddress(&count_ptr, g_count);
    cudaMemsetAsync(count_ptr, 0, (size_t)C_REP * MAX_N * sizeof(int), 0);

    hist_kernel<<<(E + 255) / 256, 256>>>(adj_rows, E);
    reduce_kernel<<<(N + 255) / 256, 256>>>(N);
    scan_kernel<<<1, SCAN_THREADS>>>(N);
    stagger_kernel<<<(N + 255) / 256, 256>>>(N);
    scatter_kernel<<<(E + 255) / 256, 256>>>(adj_rows, adj_cols, adj_vals, E);

    long long total_threads = (long long)N * 32;
    int blocks = (int)((total_threads + 255) / 256);
    spmm_csr_kernel<<<blocks, 256>>>((const float4*)embeds, (float4*)out, N);
}

// round 7
// speedup vs baseline: 1.9975x; 1.1261x over previous
#include <cuda_runtime.h>
#include <cuda_bf16.h>

// GCNLayer SpMM: out[i,:] = sum_{e: rows[e]==i} vals[e] * embeds[cols[e],:]
// N=10000 nodes, E=640000 edges, D=128 features.
//
// Round-7: counting-sort CSR build with 32-way replicated counters in
// TRANSPOSED layout g_count[r][c] so every replica-processing kernel is
// warp-per-row and coalesced. Round-6's stagger (1 thread/row, serial chain
// of 32 strided L2 round-trips, 19.2us @ issue=0.8%) becomes a warp shfl
// exclusive scan (~1us); reduce becomes __reduce_add_sync (~1us). Hist and
// scatter use replica=lane (e&31): zero intra-warp same-address conflicts,
// ~2-deep cross-warp contention. Main SpMM: warp-per-row CSR gather,
// register accumulation, zero atomics -> L2-read floor ~29us.

static constexpr int MAX_N = 10000;
static constexpr int MAX_E = 640000;
static constexpr int D_VEC = 32;           // 128 floats = 32 float4 per row
static constexpr int C_REP = 32;           // counter replication factor

__device__ int   g_count[MAX_N * C_REP];   // [row][replica]
__device__ int   g_cursor[MAX_N * C_REP];  // [row][replica] staggered cursors
__device__ int   g_total[MAX_N];           // per-row totals
__device__ int   g_start[MAX_N + 1];       // CSR row offsets
__device__ uint2 g_pairs[MAX_E];           // .x = col, .y = bits(val), row-sorted

// ---------------------------------------------------------------- hist
// No-return atomicAdd -> RED. replica = e&31: each lane of a warp hits a
// different word of row r's 128B counter group -> no intra-warp conflicts.
__global__ void hist_kernel(const int* __restrict__ rows, int E) {
    int e = blockIdx.x * blockDim.x + threadIdx.x;
    if (e < E) {
        int r = rows[e];
        atomicAdd(&g_count[r * C_REP + (e & (C_REP - 1))], 1);
    }
}

// ---------------------------------------------------------------- reduce
// Warp per row, coalesced 128B load, warp-sum -> g_total[r].
__global__ void reduce_kernel(int n) {
    int warp = (blockIdx.x * blockDim.x + threadIdx.x) >> 5;
    int lane = threadIdx.x & 31;
    if (warp >= n) return;
    int c = g_count[warp * C_REP + lane];
    int t = __reduce_add_sync(0xffffffffu, c);
    if (lane == 0) g_total[warp] = t;
}

// ---------------------------------------------------------------- scan
// Single block, smem-staged, coalesced, register-light.
static constexpr int SCAN_THREADS = 1024;
static constexpr int SCAN_ITEMS   = 10;     // 10240 >= N
static constexpr int SCAN_SPAN    = SCAN_THREADS * SCAN_ITEMS;

__global__ __launch_bounds__(SCAN_THREADS) void scan_kernel(int n) {
    __shared__ int s_val[SCAN_SPAN];
    __shared__ int s_part[SCAN_THREADS];
    int tid = threadIdx.x;

    for (int i = tid; i < SCAN_SPAN; i += SCAN_THREADS)
        s_val[i] = (i < n) ? g_total[i] : 0;
    __syncthreads();

    int base = tid * SCAN_ITEMS;
    int loc[SCAN_ITEMS];
    int sum = 0;
    #pragma unroll
    for (int i = 0; i < SCAN_ITEMS; i++) { loc[i] = sum; sum += s_val[base + i]; }
    s_part[tid] = sum;
    __syncthreads();

    for (int off = 1; off < SCAN_THREADS; off <<= 1) {
        int t = (tid >= off) ? s_part[tid - off] : 0;
        __syncthreads();
        s_part[tid] += t;
        __syncthreads();
    }

    int prefix = (tid > 0) ? s_part[tid - 1] : 0;
    #pragma unroll
    for (int i = 0; i < SCAN_ITEMS; i++) s_val[base + i] = prefix + loc[i];
    __syncthreads();

    for (int i = tid; i < n; i += SCAN_THREADS) g_start[i] = s_val[i];
    if (tid == SCAN_THREADS - 1) g_start[n] = s_part[SCAN_THREADS - 1];
}

// ---------------------------------------------------------------- stagger
// Warp per row: shfl exclusive scan over the 32 replica counts.
__global__ void stagger_kernel(int n) {
    int warp = (blockIdx.x * blockDim.x + threadIdx.x) >> 5;
    int lane = threadIdx.x & 31;
    if (warp >= n) return;

    int cnt = g_count[warp * C_REP + lane];
    int x = cnt;
    #pragma unroll
    for (int off = 1; off < 32; off <<= 1) {
        int t = __shfl_up_sync(0xffffffffu, x, off);
        if (lane >= off) x += t;
    }
    int excl = x - cnt;                       // exclusive prefix
    g_cursor[warp * C_REP + lane] = g_start[warp] + excl;
}

// ---------------------------------------------------------------- scatter
// Returning atomic; ~2-deep contention over 320K cursor addresses.
__global__ void scatter_kernel(const int*   __restrict__ rows,
                               const int*   __restrict__ cols,
                               const float* __restrict__ vals,
                               int E) {
    int e = blockIdx.x * blockDim.x + threadIdx.x;
    if (e >= E) return;
    int r = rows[e];
    int pos = atomicAdd(&g_cursor[r * C_REP + (e & (C_REP - 1))], 1);
    g_pairs[pos] = make_uint2((unsigned)cols[e], __float_as_uint(vals[e]));
}

// ---------------------------------------------------------------- spmm
// Warp per row: lane owns one float4 (16B) chunk of the 512B output row.
__global__ __launch_bounds__(256) void spmm_csr_kernel(
    const float4* __restrict__ emb,    // [N, 32] float4
    float4*       __restrict__ out,    // [N, 32] float4
    int n)
{
    int warp = (blockIdx.x * blockDim.x + threadIdx.x) >> 5;
    int lane = threadIdx.x & 31;
    if (warp >= n) return;

    int j   = g_start[warp];
    int end = g_start[warp + 1];

    float4 acc = make_float4(0.f, 0.f, 0.f, 0.f);

    while (end - j >= 32) {
        uint2 p = g_pairs[j + lane];
        #pragma unroll 8
        for (int k = 0; k < 32; k++) {
            int   c = __shfl_sync(0xffffffffu, (int)p.x, k);
            float v = __uint_as_float(__shfl_sync(0xffffffffu, p.y, k));
            float4 x = __ldg(emb + c * D_VEC + lane);
            acc.x += v * x.x; acc.y += v * x.y;
            acc.z += v * x.z; acc.w += v * x.w;
        }
        j += 32;
    }

    int m = end - j;
    if (m > 0) {
        uint2 p = (lane < m) ? g_pairs[j + lane] : make_uint2(0u, 0u);
        for (int k = 0; k < m; k++) {
            int   c = __shfl_sync(0xffffffffu, (int)p.x, k);
            float v = __uint_as_float(__shfl_sync(0xffffffffu, p.y, k));
            float4 x = __ldg(emb + c * D_VEC + lane);
            acc.x += v * x.x; acc.y += v * x.y;
            acc.z += v * x.z; acc.w += v * x.w;
        }
    }

    out[warp * D_VEC + lane] = acc;   // rows with no edges write zeros
}

// ----------------------------------------------------------------- launch
extern "C" void kernel_launch(void* const* d_in, const int* in_sizes, int n_in,
                              void* d_out, int out_size) {
    const int*   adj_rows = (const int*)  d_in[0];
    const int*   adj_cols = (const int*)  d_in[1];
    const float* adj_vals = (const float*)d_in[2];
    const float* embeds   = (const float*)d_in[3];
    float*       out      = (float*)d_out;

    const int E = in_sizes[0];           // 640000
    const int N = out_size / 128;        // 10000

    // Zero the replicated histograms via a memset node (capture-legal).
    void* count_ptr = nullptr;
    cudaGetSymbolAddress(&count_ptr, g_count);
    cudaMemsetAsync(count_ptr, 0, (size_t)MAX_N * C_REP * sizeof(int), 0);

    hist_kernel<<<(E + 255) / 256, 256>>>(adj_rows, E);

    long long warp_threads = (long long)N * 32;
    int warp_blocks = (int)((warp_threads + 255) / 256);
    reduce_kernel<<<warp_blocks, 256>>>(N);
    scan_kernel<<<1, SCAN_THREADS>>>(N);
    stagger_kernel<<<warp_blocks, 256>>>(N);
    scatter_kernel<<<(E + 255) / 256, 256>>>(adj_rows, adj_cols, adj_vals, E);

    spmm_csr_kernel<<<warp_blocks, 256>>>((const float4*)embeds, (float4*)out, N);
}